// round 2
// baseline (speedup 1.0000x reference)
#include <cuda_runtime.h>
#include <cstdint>

// ---------------- problem constants ----------------
#define D_    768
#define H_    3072
#define E_    8
#define MAXPE 4096   // max tokens per expert (each token picks distinct experts)
#define NMAX  4096

// ---------------- device scratch (no allocations allowed) ----------------
__device__ float g_h[(size_t)E_ * MAXPE * H_];   // per-assignment hidden acts (relu^2 applied)
__device__ int   g_tok[E_ * MAXPE];              // token id per (expert, slot)
__device__ float g_wt[E_ * MAXPE];               // routing weight per (expert, slot)
__device__ float g_probs[(size_t)NMAX * E_];     // softmax probs for loss
__device__ int   g_cnt[E_];                      // tokens per expert
__device__ float g_sumprob[E_];                  // column sums of probs

// ---------------- packed fp32x2 helpers (B300 FFMA2 path) ----------------
__device__ __forceinline__ void ffma2(unsigned long long& d, unsigned long long a,
                                      unsigned long long b) {
    asm("fma.rn.f32x2 %0, %1, %2, %0;" : "+l"(d) : "l"(a), "l"(b));
}
__device__ __forceinline__ unsigned long long pack2(float lo, float hi) {
    unsigned long long r;
    asm("mov.b64 %0, {%1, %2};" : "=l"(r) : "f"(lo), "f"(hi));
    return r;
}
__device__ __forceinline__ void unpack2(unsigned long long v, float& lo, float& hi) {
    asm("mov.b64 {%0, %1}, %2;" : "=f"(lo), "=f"(hi) : "l"(v));
}

// ---------------- kernel 0: zero output + counters ----------------
__global__ void zero_kernel(float* __restrict__ out, int out_size) {
    for (int i = blockIdx.x * blockDim.x + threadIdx.x; i < out_size;
         i += gridDim.x * blockDim.x)
        out[i] = 0.0f;
    if (blockIdx.x == 0 && threadIdx.x < E_) g_cnt[threadIdx.x] = 0;
}

// ---------------- kernel 1: gating (one warp per token) ----------------
__global__ __launch_bounds__(256) void gate_kernel(const float* __restrict__ x,
                                                   const float* __restrict__ gw,
                                                   int N) {
    int token = blockIdx.x * 8 + (threadIdx.x >> 5);
    int lane  = threadIdx.x & 31;
    if (token >= N) return;

    const float* xr = x + (size_t)token * D_;
    float xs[D_ / 32];
#pragma unroll
    for (int i = 0; i < D_ / 32; i++) xs[i] = xr[lane + i * 32];

    float p[E_];
#pragma unroll
    for (int e = 0; e < E_; e++) {
        const float* g = gw + e * D_;
        float s = 0.0f;
#pragma unroll
        for (int i = 0; i < D_ / 32; i++) s += xs[i] * g[lane + i * 32];
#pragma unroll
        for (int o = 16; o; o >>= 1) s += __shfl_xor_sync(0xffffffffu, s, o);
        p[e] = s;
    }

    if (lane == 0) {
        float mx = p[0];
#pragma unroll
        for (int e = 1; e < E_; e++) mx = fmaxf(mx, p[e]);
        float sum = 0.0f;
#pragma unroll
        for (int e = 0; e < E_; e++) { p[e] = expf(p[e] - mx); sum += p[e]; }
        float inv = 1.0f / sum;
#pragma unroll
        for (int e = 0; e < E_; e++) {
            p[e] *= inv;
            g_probs[(size_t)token * E_ + e] = p[e];
        }
        // top-2 (lowest index wins ties, matching lax.top_k)
        int i1 = 0;
#pragma unroll
        for (int e = 1; e < E_; e++) if (p[e] > p[i1]) i1 = e;
        int i2 = (i1 == 0) ? 1 : 0;
#pragma unroll
        for (int e = 0; e < E_; e++) if (e != i1 && p[e] > p[i2]) i2 = e;
        float s2 = p[i1] + p[i2];
        float w1 = p[i1] / s2, w2 = p[i2] / s2;

        int pos = atomicAdd(&g_cnt[i1], 1);
        g_tok[i1 * MAXPE + pos] = token; g_wt[i1 * MAXPE + pos] = w1;
        pos = atomicAdd(&g_cnt[i2], 1);
        g_tok[i2 * MAXPE + pos] = token; g_wt[i2 * MAXPE + pos] = w2;
    }
}

// ---------------- kernel 2: deterministic column-sum of probs ----------------
__global__ void reduce_probs_kernel(int N) {
    __shared__ float sm[256];
    int e = blockIdx.x;
    float s = 0.0f;
    for (int i = threadIdx.x; i < N; i += 256) s += g_probs[(size_t)i * E_ + e];
    sm[threadIdx.x] = s;
    __syncthreads();
    for (int o = 128; o; o >>= 1) {
        if (threadIdx.x < o) sm[threadIdx.x] += sm[threadIdx.x + o];
        __syncthreads();
    }
    if (threadIdx.x == 0) g_sumprob[e] = sm[0];
}

// ---------------- grouped GEMM: 128x128x16 tile, 8x8 micro, FFMA2 ----------------
// MODE 0: h = relu(x @ w_fc^T)^2 -> g_h      (A gathered token rows, Kdim = D_)
// MODE 1: out += wt * (g_h @ w_proj^T)       (A = g_h rows,        Kdim = H_)
template <int MODE>
__global__ __launch_bounds__(256) void moe_gemm(const float* __restrict__ x,
                                                const float* __restrict__ W,
                                                float* __restrict__ out,
                                                int Kdim) {
    const int e    = blockIdx.z;
    const int cntE = g_cnt[e];
    const int m0   = blockIdx.x * 128;
    if (m0 >= cntE) return;
    const int n0 = blockIdx.y * 128;

    __shared__ __align__(16) float As[2][16][128];
    __shared__ __align__(16) float Bs[2][16][128];

    const int tid  = threadIdx.x;
    const int lrow = tid >> 2;         // 0..63
    const int lcol = (tid & 3) << 2;   // 0,4,8,12
    const int tx   = tid & 15;
    const int ty   = tid >> 4;

    const float* aptr[2];
    const float* bptr[2];
#pragma unroll
    for (int i = 0; i < 2; i++) {
        int m = m0 + lrow + i * 64;
        if (MODE == 0)
            aptr[i] = (m < cntE) ? (x + (size_t)g_tok[e * MAXPE + m] * D_) : nullptr;
        else
            aptr[i] = (m < cntE) ? (g_h + ((size_t)e * MAXPE + m) * H_) : nullptr;
        int n = n0 + lrow + i * 64;
        bptr[i] = W + (size_t)e * ((size_t)H_ * D_) + (size_t)n * Kdim;
    }

    unsigned long long acc[8][4];
#pragma unroll
    for (int i = 0; i < 8; i++)
#pragma unroll
        for (int j = 0; j < 4; j++) acc[i][j] = 0ull;

    float4 sa[2], sb[2];
    const float4 z4 = make_float4(0.f, 0.f, 0.f, 0.f);

    // prologue: tile 0
#pragma unroll
    for (int i = 0; i < 2; i++) {
        sa[i] = aptr[i] ? *(const float4*)(aptr[i] + lcol) : z4;
        sb[i] = *(const float4*)(bptr[i] + lcol);
    }
#pragma unroll
    for (int i = 0; i < 2; i++) {
        int r = lrow + i * 64;
        As[0][lcol + 0][r] = sa[i].x; As[0][lcol + 1][r] = sa[i].y;
        As[0][lcol + 2][r] = sa[i].z; As[0][lcol + 3][r] = sa[i].w;
        Bs[0][lcol + 0][r] = sb[i].x; Bs[0][lcol + 1][r] = sb[i].y;
        Bs[0][lcol + 2][r] = sb[i].z; Bs[0][lcol + 3][r] = sb[i].w;
    }
    __syncthreads();

    const int nk = Kdim / 16;
    int cur = 0;
    for (int kt = 0; kt < nk; ++kt) {
        if (kt + 1 < nk) {
            int k = (kt + 1) * 16 + lcol;
#pragma unroll
            for (int i = 0; i < 2; i++) {
                sa[i] = aptr[i] ? *(const float4*)(aptr[i] + k) : z4;
                sb[i] = *(const float4*)(bptr[i] + k);
            }
        }
#pragma unroll
        for (int kk = 0; kk < 16; ++kk) {
            float4 a0 = *(const float4*)&As[cur][kk][ty * 4];
            float4 a1 = *(const float4*)&As[cur][kk][ty * 4 + 64];
            ulonglong2 b0 = *(const ulonglong2*)&Bs[cur][kk][tx * 4];
            ulonglong2 b1 = *(const ulonglong2*)&Bs[cur][kk][tx * 4 + 64];
            float af[8] = {a0.x, a0.y, a0.z, a0.w, a1.x, a1.y, a1.z, a1.w};
#pragma unroll
            for (int i = 0; i < 8; i++) {
                unsigned long long ap = pack2(af[i], af[i]);
                ffma2(acc[i][0], ap, b0.x);
                ffma2(acc[i][1], ap, b0.y);
                ffma2(acc[i][2], ap, b1.x);
                ffma2(acc[i][3], ap, b1.y);
            }
        }
        if (kt + 1 < nk) {
            int nxt = cur ^ 1;
#pragma unroll
            for (int i = 0; i < 2; i++) {
                int r = lrow + i * 64;
                As[nxt][lcol + 0][r] = sa[i].x; As[nxt][lcol + 1][r] = sa[i].y;
                As[nxt][lcol + 2][r] = sa[i].z; As[nxt][lcol + 3][r] = sa[i].w;
                Bs[nxt][lcol + 0][r] = sb[i].x; Bs[nxt][lcol + 1][r] = sb[i].y;
                Bs[nxt][lcol + 2][r] = sb[i].z; Bs[nxt][lcol + 3][r] = sb[i].w;
            }
            __syncthreads();
            cur = nxt;
        }
    }

    // epilogue
#pragma unroll
    for (int gi = 0; gi < 2; ++gi)
#pragma unroll
        for (int i = 0; i < 4; ++i) {
            int r = ty * 4 + i + gi * 64;
            int m = m0 + r;
            if (m >= cntE) continue;
            int ai = gi * 4 + i;
            float v[8];
            unpack2(acc[ai][0], v[0], v[1]);
            unpack2(acc[ai][1], v[2], v[3]);
            unpack2(acc[ai][2], v[4], v[5]);
            unpack2(acc[ai][3], v[6], v[7]);
            if (MODE == 0) {
                float* dst = g_h + ((size_t)e * MAXPE + m) * H_ + n0;
#pragma unroll
                for (int gj = 0; gj < 2; gj++) {
                    float4 o;
                    float t;
                    t = fmaxf(v[gj * 4 + 0], 0.f); o.x = t * t;
                    t = fmaxf(v[gj * 4 + 1], 0.f); o.y = t * t;
                    t = fmaxf(v[gj * 4 + 2], 0.f); o.z = t * t;
                    t = fmaxf(v[gj * 4 + 3], 0.f); o.w = t * t;
                    *(float4*)(dst + tx * 4 + gj * 64) = o;
                }
            } else {
                int tok  = g_tok[e * MAXPE + m];
                float wt = g_wt[e * MAXPE + m];
                float* orow = out + (size_t)tok * D_ + n0;
#pragma unroll
                for (int gj = 0; gj < 2; gj++)
#pragma unroll
                    for (int j = 0; j < 4; j++)
                        atomicAdd(orow + tx * 4 + gj * 64 + j, wt * v[gj * 4 + j]);
            }
        }
}

// ---------------- kernel 5: balance loss scalar ----------------
__global__ void loss_kernel(float* __restrict__ out, int N, int out_size) {
    if (out_size <= N * D_) return;
    float loss = 0.0f;
    for (int e = 0; e < E_; e++)
        loss += (g_sumprob[e] / (float)N) * ((float)g_cnt[e] / (float)N);
    out[(size_t)N * D_] = loss * (float)E_;
}

// ---------------- launch ----------------
extern "C" void kernel_launch(void* const* d_in, const int* in_sizes, int n_in,
                              void* d_out, int out_size) {
    const float* x     = (const float*)d_in[0];
    const float* gw    = (const float*)d_in[1];
    const float* wfc   = (const float*)d_in[2];
    const float* wproj = (const float*)d_in[3];
    float* out = (float*)d_out;
    int N = in_sizes[0] / D_;   // 4096

    zero_kernel<<<1024, 256>>>(out, out_size);
    gate_kernel<<<(N + 7) / 8, 256>>>(x, gw, N);
    reduce_probs_kernel<<<E_, 256>>>(N);

    dim3 g1((N + 127) / 128, H_ / 128, E_);
    moe_gemm<0><<<g1, 256>>>(x, wfc, nullptr, D_);

    dim3 g2((N + 127) / 128, D_ / 128, E_);
    moe_gemm<1><<<g2, 256>>>(nullptr, wproj, out, H_);

    loss_kernel<<<1, 1>>>(out, N, out_size);
}

// round 5
// speedup vs baseline: 1.4050x; 1.4050x over previous
#include <cuda_runtime.h>
#include <cuda_bf16.h>
#include <cstdint>

// ---------------- problem constants ----------------
#define D_    768
#define H_    3072
#define E_    8
#define MAXPE 4096
#define NMAX  4096

#define BM 128
#define BN 128
#define BK 32

// ---------------- device scratch ----------------
__device__ float g_h[(size_t)E_ * MAXPE * H_];   // fp32 hidden acts (relu^2 applied)
__device__ int   g_tok[E_ * MAXPE];
__device__ float g_wt[E_ * MAXPE];
__device__ float g_probs[(size_t)NMAX * E_];
__device__ int   g_cnt[E_];
__device__ float g_sumprob[E_];

// ---------------- helpers ----------------
__device__ __forceinline__ uint32_t smem_u32(const void* p) {
    uint32_t a;
    asm("{ .reg .u64 t; cvta.to.shared.u64 t, %1; cvt.u32.u64 %0, t; }" : "=r"(a) : "l"(p));
    return a;
}
__device__ __forceinline__ void ldsm4(uint32_t* r, uint32_t addr) {
    asm volatile("ldmatrix.sync.aligned.m8n8.x4.shared.b16 {%0,%1,%2,%3}, [%4];"
                 : "=r"(r[0]), "=r"(r[1]), "=r"(r[2]), "=r"(r[3]) : "r"(addr));
}
__device__ __forceinline__ void mma_bf16(float* c, const uint32_t* a, uint32_t b0, uint32_t b1) {
    asm volatile("mma.sync.aligned.m16n8k16.row.col.f32.bf16.bf16.f32 "
                 "{%0,%1,%2,%3}, {%4,%5,%6,%7}, {%8,%9}, {%0,%1,%2,%3};"
                 : "+f"(c[0]), "+f"(c[1]), "+f"(c[2]), "+f"(c[3])
                 : "r"(a[0]), "r"(a[1]), "r"(a[2]), "r"(a[3]), "r"(b0), "r"(b1));
}
// split one float4 into hi-bf16 pair-regs and lo-bf16 pair-regs
__device__ __forceinline__ void cvt_split(float4 v, uint32_t& h0, uint32_t& h1,
                                          uint32_t& l0, uint32_t& l1) {
    __nv_bfloat162 a = __floats2bfloat162_rn(v.x, v.y);
    __nv_bfloat162 b = __floats2bfloat162_rn(v.z, v.w);
    h0 = *reinterpret_cast<uint32_t*>(&a);
    h1 = *reinterpret_cast<uint32_t*>(&b);
    float f0 = __uint_as_float(h0 << 16);
    float f1 = __uint_as_float(h0 & 0xffff0000u);
    float f2 = __uint_as_float(h1 << 16);
    float f3 = __uint_as_float(h1 & 0xffff0000u);
    __nv_bfloat162 c = __floats2bfloat162_rn(v.x - f0, v.y - f1);
    __nv_bfloat162 d = __floats2bfloat162_rn(v.z - f2, v.w - f3);
    l0 = *reinterpret_cast<uint32_t*>(&c);
    l1 = *reinterpret_cast<uint32_t*>(&d);
}
__device__ __forceinline__ void sts_v4(uint32_t addr, uint32_t a, uint32_t b, uint32_t c,
                                       uint32_t d) {
    asm volatile("st.shared.v4.b32 [%0], {%1, %2, %3, %4};"
                 :: "r"(addr), "r"(a), "r"(b), "r"(c), "r"(d));
}

// ---------------- kernel 0: zero output + counters ----------------
__global__ void zero_kernel(float* __restrict__ out, int out_size) {
    for (int i = blockIdx.x * blockDim.x + threadIdx.x; i < out_size;
         i += gridDim.x * blockDim.x)
        out[i] = 0.0f;
    if (blockIdx.x == 0 && threadIdx.x < E_) g_cnt[threadIdx.x] = 0;
}

// ---------------- kernel 1: gating ----------------
__global__ __launch_bounds__(256) void gate_kernel(const float* __restrict__ x,
                                                   const float* __restrict__ gw,
                                                   int N) {
    int token = blockIdx.x * 8 + (threadIdx.x >> 5);
    int lane  = threadIdx.x & 31;
    if (token >= N) return;

    const float* xr = x + (size_t)token * D_;
    float xs[D_ / 32];
#pragma unroll
    for (int i = 0; i < D_ / 32; i++) xs[i] = xr[lane + i * 32];

    float p[E_];
#pragma unroll
    for (int e = 0; e < E_; e++) {
        const float* g = gw + e * D_;
        float s = 0.0f;
#pragma unroll
        for (int i = 0; i < D_ / 32; i++) s += xs[i] * g[lane + i * 32];
#pragma unroll
        for (int o = 16; o; o >>= 1) s += __shfl_xor_sync(0xffffffffu, s, o);
        p[e] = s;
    }

    if (lane == 0) {
        float mx = p[0];
#pragma unroll
        for (int e = 1; e < E_; e++) mx = fmaxf(mx, p[e]);
        float sum = 0.0f;
#pragma unroll
        for (int e = 0; e < E_; e++) { p[e] = expf(p[e] - mx); sum += p[e]; }
        float inv = 1.0f / sum;
#pragma unroll
        for (int e = 0; e < E_; e++) {
            p[e] *= inv;
            g_probs[(size_t)token * E_ + e] = p[e];
        }
        int i1 = 0;
#pragma unroll
        for (int e = 1; e < E_; e++) if (p[e] > p[i1]) i1 = e;
        int i2 = (i1 == 0) ? 1 : 0;
#pragma unroll
        for (int e = 0; e < E_; e++) if (e != i1 && p[e] > p[i2]) i2 = e;
        float s2 = p[i1] + p[i2];
        float w1 = p[i1] / s2, w2 = p[i2] / s2;

        int pos = atomicAdd(&g_cnt[i1], 1);
        g_tok[i1 * MAXPE + pos] = token; g_wt[i1 * MAXPE + pos] = w1;
        pos = atomicAdd(&g_cnt[i2], 1);
        g_tok[i2 * MAXPE + pos] = token; g_wt[i2 * MAXPE + pos] = w2;
    }
}

// ---------------- kernel 2: deterministic column-sum of probs ----------------
__global__ void reduce_probs_kernel(int N) {
    __shared__ float sm[256];
    int e = blockIdx.x;
    float s = 0.0f;
    for (int i = threadIdx.x; i < N; i += 256) s += g_probs[(size_t)i * E_ + e];
    sm[threadIdx.x] = s;
    __syncthreads();
    for (int o = 128; o; o >>= 1) {
        if (threadIdx.x < o) sm[threadIdx.x] += sm[threadIdx.x + o];
        __syncthreads();
    }
    if (threadIdx.x == 0) g_sumprob[e] = sm[0];
}

// ---------------- grouped GEMM via mma.sync bf16x3 ----------------
// SMEM stage (32KB): A_hi[128][32]bf16 @0, A_lo @8192, B_hi @16384, B_lo @24576
// 2 stages -> 64KB dynamic.
// MODE 0: h = relu(x_gathered @ w_fc^T)^2 -> g_h   (Kdim = D_)
// MODE 1: out += wt * (g_h @ w_proj^T)  (atomicAdd) (Kdim = H_)
#define STAGE_BYTES 32768u
#define SMEM_TOTAL  (2 * STAGE_BYTES)

template <int MODE>
__global__ __launch_bounds__(256, 1) void moe_gemm_mma(const float* __restrict__ X,
                                                       const float* __restrict__ W,
                                                       float* __restrict__ out,
                                                       int Kdim) {
    const int e   = blockIdx.z;
    const int cnt = g_cnt[e];
    const int m0  = blockIdx.y * BM;
    if (m0 >= cnt) return;
    const int n0 = blockIdx.x * BN;

    extern __shared__ __align__(128) char smem[];
    const uint32_t sb = smem_u32(smem);

    const int tid  = threadIdx.x;
    const int warp = tid >> 5, lane = tid & 31;
    const int wm = warp >> 2, wn = warp & 3;  // 2 x 4 warp grid, warp tile 64x32

    // ---- loader mapping: 2 threads per row, 16 floats each ----
    const int lrow  = tid >> 1;
    const int lhalf = tid & 1;
    const float* a_src;
    if (MODE == 0) {
        int m   = m0 + lrow;
        int tok = g_tok[e * MAXPE + ((m < cnt) ? m : m0)];
        a_src = X + (size_t)tok * D_ + lhalf * 16;
    } else {
        a_src = g_h + ((size_t)(e * MAXPE + m0 + lrow)) * H_ + lhalf * 16;
    }
    const float* b_src =
        W + (size_t)e * ((size_t)H_ * D_) + (size_t)(n0 + lrow) * Kdim + lhalf * 16;
    const uint32_t st_off = (uint32_t)lrow * 64u + (uint32_t)lhalf * 32u;

    // ---- ldmatrix per-lane addresses ----
    const uint32_t a_ld = (uint32_t)(wm * 64 + (lane & 15)) * 64u + (uint32_t)(lane >> 4) * 16u;
    const uint32_t b_ld =
        (uint32_t)(wn * 32 + ((lane >> 4) & 1) * 8 + (lane & 7)) * 64u +
        (uint32_t)((lane >> 3) & 1) * 16u;

    float acc[64];
#pragma unroll
    for (int i = 0; i < 64; i++) acc[i] = 0.0f;

    const int nk = Kdim / BK;
    float4 ra[4], rb[4];

    // prologue: load k-tile 0
    {
        const float4* ap = (const float4*)a_src;
        const float4* bp = (const float4*)b_src;
#pragma unroll
        for (int i = 0; i < 4; i++) { ra[i] = ap[i]; rb[i] = bp[i]; }
        uint32_t h[8], l[8];
#pragma unroll
        for (int i = 0; i < 4; i++) cvt_split(ra[i], h[2 * i], h[2 * i + 1], l[2 * i], l[2 * i + 1]);
        sts_v4(sb + st_off, h[0], h[1], h[2], h[3]);
        sts_v4(sb + st_off + 16, h[4], h[5], h[6], h[7]);
        sts_v4(sb + 8192 + st_off, l[0], l[1], l[2], l[3]);
        sts_v4(sb + 8192 + st_off + 16, l[4], l[5], l[6], l[7]);
#pragma unroll
        for (int i = 0; i < 4; i++) cvt_split(rb[i], h[2 * i], h[2 * i + 1], l[2 * i], l[2 * i + 1]);
        sts_v4(sb + 16384 + st_off, h[0], h[1], h[2], h[3]);
        sts_v4(sb + 16384 + st_off + 16, h[4], h[5], h[6], h[7]);
        sts_v4(sb + 24576 + st_off, l[0], l[1], l[2], l[3]);
        sts_v4(sb + 24576 + st_off + 16, l[4], l[5], l[6], l[7]);
    }
    __syncthreads();

    for (int kt = 0; kt < nk; ++kt) {
        const uint32_t base = sb + (uint32_t)(kt & 1) * STAGE_BYTES;
        // prefetch next k-tile into regs
        if (kt + 1 < nk) {
            const float4* ap = (const float4*)(a_src + (kt + 1) * BK);
            const float4* bp = (const float4*)(b_src + (kt + 1) * BK);
#pragma unroll
            for (int i = 0; i < 4; i++) { ra[i] = ap[i]; rb[i] = bp[i]; }
        }
        // ---- MMA on current stage ----
#pragma unroll
        for (int ks = 0; ks < 2; ks++) {
            uint32_t ah[4][4], al[4][4], bh[2][4], bl[2][4];
            const uint32_t abase = base + a_ld + ks * 32;
            const uint32_t bbase = base + 16384 + b_ld + ks * 32;
#pragma unroll
            for (int am = 0; am < 4; am++) {
                ldsm4(ah[am], abase + am * 1024);
                ldsm4(al[am], abase + 8192 + am * 1024);
            }
#pragma unroll
            for (int g = 0; g < 2; g++) {
                ldsm4(bh[g], bbase + g * 1024);
                ldsm4(bl[g], bbase + 8192 + g * 1024);
            }
#pragma unroll
            for (int am = 0; am < 4; am++)
#pragma unroll
                for (int an = 0; an < 4; an++) {
                    float* c = &acc[(am * 4 + an) * 4];
                    const int g = an >> 1, p = (an & 1) * 2;
                    mma_bf16(c, ah[am], bh[g][p], bh[g][p + 1]);
                    mma_bf16(c, ah[am], bl[g][p], bl[g][p + 1]);
                    mma_bf16(c, al[am], bh[g][p], bh[g][p + 1]);
                }
        }
        // ---- store next stage ----
        if (kt + 1 < nk) {
            const uint32_t nbase = sb + (uint32_t)((kt + 1) & 1) * STAGE_BYTES;
            uint32_t h[8], l[8];
#pragma unroll
            for (int i = 0; i < 4; i++)
                cvt_split(ra[i], h[2 * i], h[2 * i + 1], l[2 * i], l[2 * i + 1]);
            sts_v4(nbase + st_off, h[0], h[1], h[2], h[3]);
            sts_v4(nbase + st_off + 16, h[4], h[5], h[6], h[7]);
            sts_v4(nbase + 8192 + st_off, l[0], l[1], l[2], l[3]);
            sts_v4(nbase + 8192 + st_off + 16, l[4], l[5], l[6], l[7]);
#pragma unroll
            for (int i = 0; i < 4; i++)
                cvt_split(rb[i], h[2 * i], h[2 * i + 1], l[2 * i], l[2 * i + 1]);
            sts_v4(nbase + 16384 + st_off, h[0], h[1], h[2], h[3]);
            sts_v4(nbase + 16384 + st_off + 16, h[4], h[5], h[6], h[7]);
            sts_v4(nbase + 24576 + st_off, l[0], l[1], l[2], l[3]);
            sts_v4(nbase + 24576 + st_off + 16, l[4], l[5], l[6], l[7]);
        }
        __syncthreads();
    }

    // ---- epilogue ----
    const int qr = lane >> 2;            // row within 8
    const int qc = (lane & 3) * 2;       // col pair within 8
    if (MODE == 0) {
        float* hbase = g_h + ((size_t)(e * MAXPE + m0 + wm * 64)) * H_ + n0 + wn * 32;
#pragma unroll
        for (int am = 0; am < 4; am++)
#pragma unroll
            for (int hh = 0; hh < 2; hh++) {
                float* dst = hbase + (size_t)(am * 16 + qr + hh * 8) * H_;
#pragma unroll
                for (int an = 0; an < 4; an++) {
                    const float* c = &acc[(am * 4 + an) * 4 + hh * 2];
                    float t0 = fmaxf(c[0], 0.f), t1 = fmaxf(c[1], 0.f);
                    float2 o = make_float2(t0 * t0, t1 * t1);
                    *(float2*)(dst + an * 8 + qc) = o;
                }
            }
    } else {
#pragma unroll
        for (int am = 0; am < 4; am++)
#pragma unroll
            for (int hh = 0; hh < 2; hh++) {
                const int m = m0 + wm * 64 + am * 16 + qr + hh * 8;
                if (m >= cnt) continue;
                const int tok = g_tok[e * MAXPE + m];
                const float wt = g_wt[e * MAXPE + m];
                float* orow = out + (size_t)tok * D_ + n0 + wn * 32;
#pragma unroll
                for (int an = 0; an < 4; an++) {
                    const float* c = &acc[(am * 4 + an) * 4 + hh * 2];
                    atomicAdd(orow + an * 8 + qc, wt * c[0]);
                    atomicAdd(orow + an * 8 + qc + 1, wt * c[1]);
                }
            }
    }
}

// ---------------- loss ----------------
__global__ void loss_kernel(float* __restrict__ out, int N, int out_size) {
    if (out_size <= N * D_) return;
    float loss = 0.0f;
    for (int e = 0; e < E_; e++)
        loss += (g_sumprob[e] / (float)N) * ((float)g_cnt[e] / (float)N);
    out[(size_t)N * D_] = loss * (float)E_;
}

// ---------------- launch ----------------
extern "C" void kernel_launch(void* const* d_in, const int* in_sizes, int n_in,
                              void* d_out, int out_size) {
    const float* x     = (const float*)d_in[0];
    const float* gw    = (const float*)d_in[1];
    const float* wfc   = (const float*)d_in[2];
    const float* wproj = (const float*)d_in[3];
    float* out = (float*)d_out;
    int N = in_sizes[0] / D_;  // 4096

    cudaFuncSetAttribute(moe_gemm_mma<0>, cudaFuncAttributeMaxDynamicSharedMemorySize,
                         SMEM_TOTAL);
    cudaFuncSetAttribute(moe_gemm_mma<1>, cudaFuncAttributeMaxDynamicSharedMemorySize,
                         SMEM_TOTAL);

    zero_kernel<<<1024, 256>>>(out, out_size);
    gate_kernel<<<(N + 7) / 8, 256>>>(x, gw, N);
    reduce_probs_kernel<<<E_, 256>>>(N);

    // x = N-tiles (fast-varying -> A-tile L2 reuse), y = M-tiles, z = expert
    dim3 g1(H_ / BN, MAXPE / BM, E_);
    moe_gemm_mma<0><<<g1, 256, SMEM_TOTAL>>>(x, wfc, nullptr, D_);

    dim3 g2(D_ / BN, MAXPE / BM, E_);
    moe_gemm_mma<1><<<g2, 256, SMEM_TOTAL>>>(nullptr, wproj, out, H_);

    loss_kernel<<<1, 1>>>(out, N, out_size);
}

// round 6
// speedup vs baseline: 2.5024x; 1.7811x over previous
#include <cuda_runtime.h>
#include <cuda_bf16.h>
#include <cstdint>

// ---------------- problem constants ----------------
#define D_    768
#define H_    3072
#define E_    8
#define MAXPE 4096
#define NMAX  4096

#define BM 128
#define BN 128
#define BK 32

// ---------------- device scratch ----------------
__device__ float g_h[(size_t)E_ * MAXPE * H_];   // fp32 hidden acts (relu^2 applied)
__device__ int   g_tok[E_ * MAXPE];
__device__ float g_wt[E_ * MAXPE];
__device__ float g_probs[(size_t)NMAX * E_];
__device__ int   g_cnt[E_];
__device__ float g_sumprob[E_];

// ---------------- helpers ----------------
__device__ __forceinline__ uint32_t smem_u32(const void* p) {
    uint32_t a;
    asm("{ .reg .u64 t; cvta.to.shared.u64 t, %1; cvt.u32.u64 %0, t; }" : "=r"(a) : "l"(p));
    return a;
}
__device__ __forceinline__ void ldsm4(uint32_t* r, uint32_t addr) {
    asm volatile("ldmatrix.sync.aligned.m8n8.x4.shared.b16 {%0,%1,%2,%3}, [%4];"
                 : "=r"(r[0]), "=r"(r[1]), "=r"(r[2]), "=r"(r[3]) : "r"(addr));
}
__device__ __forceinline__ void mma_bf16(float* c, const uint32_t* a, uint32_t b0, uint32_t b1) {
    asm volatile("mma.sync.aligned.m16n8k16.row.col.f32.bf16.bf16.f32 "
                 "{%0,%1,%2,%3}, {%4,%5,%6,%7}, {%8,%9}, {%0,%1,%2,%3};"
                 : "+f"(c[0]), "+f"(c[1]), "+f"(c[2]), "+f"(c[3])
                 : "r"(a[0]), "r"(a[1]), "r"(a[2]), "r"(a[3]), "r"(b0), "r"(b1));
}
// split one float4 into hi-bf16 pair-regs and lo-bf16 pair-regs
__device__ __forceinline__ void cvt_split(float4 v, uint32_t& h0, uint32_t& h1,
                                          uint32_t& l0, uint32_t& l1) {
    __nv_bfloat162 a = __floats2bfloat162_rn(v.x, v.y);
    __nv_bfloat162 b = __floats2bfloat162_rn(v.z, v.w);
    h0 = *reinterpret_cast<uint32_t*>(&a);
    h1 = *reinterpret_cast<uint32_t*>(&b);
    float f0 = __uint_as_float(h0 << 16);
    float f1 = __uint_as_float(h0 & 0xffff0000u);
    float f2 = __uint_as_float(h1 << 16);
    float f3 = __uint_as_float(h1 & 0xffff0000u);
    __nv_bfloat162 c = __floats2bfloat162_rn(v.x - f0, v.y - f1);
    __nv_bfloat162 d = __floats2bfloat162_rn(v.z - f2, v.w - f3);
    l0 = *reinterpret_cast<uint32_t*>(&c);
    l1 = *reinterpret_cast<uint32_t*>(&d);
}
__device__ __forceinline__ void sts_v4(uint32_t addr, uint32_t a, uint32_t b, uint32_t c,
                                       uint32_t d) {
    asm volatile("st.shared.v4.b32 [%0], {%1, %2, %3, %4};"
                 :: "r"(addr), "r"(a), "r"(b), "r"(c), "r"(d));
}

// ---------------- kernel 0: zero output + counters ----------------
__global__ void zero_kernel(float* __restrict__ out, int out_size) {
    for (int i = blockIdx.x * blockDim.x + threadIdx.x; i < out_size;
         i += gridDim.x * blockDim.x)
        out[i] = 0.0f;
    if (blockIdx.x == 0 && threadIdx.x < E_) g_cnt[threadIdx.x] = 0;
}

// ---------------- kernel 1: gating ----------------
__global__ __launch_bounds__(256) void gate_kernel(const float* __restrict__ x,
                                                   const float* __restrict__ gw,
                                                   int N) {
    int token = blockIdx.x * 8 + (threadIdx.x >> 5);
    int lane  = threadIdx.x & 31;
    if (token >= N) return;

    const float* xr = x + (size_t)token * D_;
    float xs[D_ / 32];
#pragma unroll
    for (int i = 0; i < D_ / 32; i++) xs[i] = xr[lane + i * 32];

    float p[E_];
#pragma unroll
    for (int e = 0; e < E_; e++) {
        const float* g = gw + e * D_;
        float s = 0.0f;
#pragma unroll
        for (int i = 0; i < D_ / 32; i++) s += xs[i] * g[lane + i * 32];
#pragma unroll
        for (int o = 16; o; o >>= 1) s += __shfl_xor_sync(0xffffffffu, s, o);
        p[e] = s;
    }

    if (lane == 0) {
        float mx = p[0];
#pragma unroll
        for (int e = 1; e < E_; e++) mx = fmaxf(mx, p[e]);
        float sum = 0.0f;
#pragma unroll
        for (int e = 0; e < E_; e++) { p[e] = expf(p[e] - mx); sum += p[e]; }
        float inv = 1.0f / sum;
#pragma unroll
        for (int e = 0; e < E_; e++) {
            p[e] *= inv;
            g_probs[(size_t)token * E_ + e] = p[e];
        }
        int i1 = 0;
#pragma unroll
        for (int e = 1; e < E_; e++) if (p[e] > p[i1]) i1 = e;
        int i2 = (i1 == 0) ? 1 : 0;
#pragma unroll
        for (int e = 0; e < E_; e++) if (e != i1 && p[e] > p[i2]) i2 = e;
        float s2 = p[i1] + p[i2];
        float w1 = p[i1] / s2, w2 = p[i2] / s2;

        int pos = atomicAdd(&g_cnt[i1], 1);
        g_tok[i1 * MAXPE + pos] = token; g_wt[i1 * MAXPE + pos] = w1;
        pos = atomicAdd(&g_cnt[i2], 1);
        g_tok[i2 * MAXPE + pos] = token; g_wt[i2 * MAXPE + pos] = w2;
    }
}

// ---------------- kernel 2: deterministic column-sum of probs ----------------
__global__ void reduce_probs_kernel(int N) {
    __shared__ float sm[256];
    int e = blockIdx.x;
    float s = 0.0f;
    for (int i = threadIdx.x; i < N; i += 256) s += g_probs[(size_t)i * E_ + e];
    sm[threadIdx.x] = s;
    __syncthreads();
    for (int o = 128; o; o >>= 1) {
        if (threadIdx.x < o) sm[threadIdx.x] += sm[threadIdx.x + o];
        __syncthreads();
    }
    if (threadIdx.x == 0) g_sumprob[e] = sm[0];
}

// ---------------- grouped GEMM via mma.sync bf16x3, swizzled smem ----------------
// Stage (32KB): A_hi[128 rows x 64B] @0, A_lo @8192, B_hi @16384, B_lo @24576.
// Row = 4 chunks of 16B; chunk stored at slot s = c ^ ((row>>1)&3)  -> conflict-free
// STS and ldmatrix (slot(addr) = 4*(row&1) + s covers all 8 bank-groups per phase).
// MODE 0: h = relu(x_gathered @ w_fc^T)^2 -> g_h   (Kdim = D_)
// MODE 1: out += wt * (g_h @ w_proj^T)  (atomicAdd) (Kdim = H_)
#define STAGE_BYTES 32768u
#define SMEM_TOTAL  (2 * STAGE_BYTES)

template <int MODE>
__global__ __launch_bounds__(256, 1) void moe_gemm_mma(const float* __restrict__ X,
                                                       const float* __restrict__ W,
                                                       float* __restrict__ out,
                                                       int Kdim) {
    const int e   = blockIdx.z;
    const int cnt = g_cnt[e];
    const int m0  = blockIdx.y * BM;
    if (m0 >= cnt) return;
    const int n0 = blockIdx.x * BN;

    extern __shared__ __align__(128) char smem[];
    const uint32_t sb = smem_u32(smem);

    const int tid  = threadIdx.x;
    const int warp = tid >> 5, lane = tid & 31;
    const int wm = warp >> 2, wn = warp & 3;  // 2 x 4 warp grid, warp tile 64x32

    // ---- loader mapping: 2 threads per row, 16 floats each ----
    const int lrow  = tid >> 1;
    const int lhalf = tid & 1;
    const float* a_src;
    if (MODE == 0) {
        int m   = m0 + lrow;
        int tok = g_tok[e * MAXPE + ((m < cnt) ? m : m0)];
        a_src = X + (size_t)tok * D_ + lhalf * 16;
    } else {
        a_src = g_h + ((size_t)(e * MAXPE + m0 + lrow)) * H_ + lhalf * 16;
    }
    const float* b_src =
        W + (size_t)e * ((size_t)H_ * D_) + (size_t)(n0 + lrow) * Kdim + lhalf * 16;

    // swizzled store offsets: chunks c0 = lhalf*2, c1 = lhalf*2+1
    const uint32_t lsw    = (uint32_t)((lrow >> 1) & 3);
    const uint32_t st_c0  = (uint32_t)lrow * 64u + (((uint32_t)(lhalf * 2) ^ lsw) * 16u);
    const uint32_t st_c1  = (uint32_t)lrow * 64u + (((uint32_t)(lhalf * 2 + 1) ^ lsw) * 16u);

    // ---- ldmatrix per-lane swizzled addressing ----
    // A: row = wm*64 + am*16 + (lane&15); chunk = ks*2 + (lane>>4)
    const int      row_a = wm * 64 + (lane & 15);
    const uint32_t sw_a  = (uint32_t)((row_a >> 1) & 3);
    const uint32_t a_row = (uint32_t)row_a * 64u;
    const uint32_t ca    = (uint32_t)(lane >> 4);
    // B: row = wn*32 + ((lane>>4)&1)*8 + (lane&7) + g*16; chunk = ks*2 + ((lane>>3)&1)
    const int      row_b = wn * 32 + ((lane >> 4) & 1) * 8 + (lane & 7);
    const uint32_t sw_b  = (uint32_t)((row_b >> 1) & 3);
    const uint32_t b_row = (uint32_t)row_b * 64u;
    const uint32_t cb    = (uint32_t)((lane >> 3) & 1);

    float acc[64];
#pragma unroll
    for (int i = 0; i < 64; i++) acc[i] = 0.0f;

    const int nk = Kdim / BK;
    float4 ra[4], rb[4];

    // prologue: load k-tile 0
    {
        const float4* ap = (const float4*)a_src;
        const float4* bp = (const float4*)b_src;
#pragma unroll
        for (int i = 0; i < 4; i++) { ra[i] = ap[i]; rb[i] = bp[i]; }
        uint32_t h[8], l[8];
#pragma unroll
        for (int i = 0; i < 4; i++) cvt_split(ra[i], h[2 * i], h[2 * i + 1], l[2 * i], l[2 * i + 1]);
        sts_v4(sb + st_c0, h[0], h[1], h[2], h[3]);
        sts_v4(sb + st_c1, h[4], h[5], h[6], h[7]);
        sts_v4(sb + 8192 + st_c0, l[0], l[1], l[2], l[3]);
        sts_v4(sb + 8192 + st_c1, l[4], l[5], l[6], l[7]);
#pragma unroll
        for (int i = 0; i < 4; i++) cvt_split(rb[i], h[2 * i], h[2 * i + 1], l[2 * i], l[2 * i + 1]);
        sts_v4(sb + 16384 + st_c0, h[0], h[1], h[2], h[3]);
        sts_v4(sb + 16384 + st_c1, h[4], h[5], h[6], h[7]);
        sts_v4(sb + 24576 + st_c0, l[0], l[1], l[2], l[3]);
        sts_v4(sb + 24576 + st_c1, l[4], l[5], l[6], l[7]);
    }
    __syncthreads();

    for (int kt = 0; kt < nk; ++kt) {
        const uint32_t base = sb + (uint32_t)(kt & 1) * STAGE_BYTES;
        // prefetch next k-tile into regs
        if (kt + 1 < nk) {
            const float4* ap = (const float4*)(a_src + (kt + 1) * BK);
            const float4* bp = (const float4*)(b_src + (kt + 1) * BK);
#pragma unroll
            for (int i = 0; i < 4; i++) { ra[i] = ap[i]; rb[i] = bp[i]; }
        }
        // ---- MMA on current stage ----
#pragma unroll
        for (int ks = 0; ks < 2; ks++) {
            uint32_t ah[4][4], al[4][4], bh[2][4], bl[2][4];
            const uint32_t aoff = base + a_row + ((((uint32_t)(ks * 2) + ca) ^ sw_a) * 16u);
            const uint32_t boff =
                base + 16384 + b_row + ((((uint32_t)(ks * 2) + cb) ^ sw_b) * 16u);
#pragma unroll
            for (int am = 0; am < 4; am++) {
                ldsm4(ah[am], aoff + am * 1024);
                ldsm4(al[am], aoff + 8192 + am * 1024);
            }
#pragma unroll
            for (int g = 0; g < 2; g++) {
                ldsm4(bh[g], boff + g * 1024);
                ldsm4(bl[g], boff + 8192 + g * 1024);
            }
#pragma unroll
            for (int am = 0; am < 4; am++)
#pragma unroll
                for (int an = 0; an < 4; an++) {
                    float* c = &acc[(am * 4 + an) * 4];
                    const int g = an >> 1, p = (an & 1) * 2;
                    mma_bf16(c, ah[am], bh[g][p], bh[g][p + 1]);
                    mma_bf16(c, ah[am], bl[g][p], bl[g][p + 1]);
                    mma_bf16(c, al[am], bh[g][p], bh[g][p + 1]);
                }
        }
        // ---- store next stage ----
        if (kt + 1 < nk) {
            const uint32_t nbase = sb + (uint32_t)((kt + 1) & 1) * STAGE_BYTES;
            uint32_t h[8], l[8];
#pragma unroll
            for (int i = 0; i < 4; i++)
                cvt_split(ra[i], h[2 * i], h[2 * i + 1], l[2 * i], l[2 * i + 1]);
            sts_v4(nbase + st_c0, h[0], h[1], h[2], h[3]);
            sts_v4(nbase + st_c1, h[4], h[5], h[6], h[7]);
            sts_v4(nbase + 8192 + st_c0, l[0], l[1], l[2], l[3]);
            sts_v4(nbase + 8192 + st_c1, l[4], l[5], l[6], l[7]);
#pragma unroll
            for (int i = 0; i < 4; i++)
                cvt_split(rb[i], h[2 * i], h[2 * i + 1], l[2 * i], l[2 * i + 1]);
            sts_v4(nbase + 16384 + st_c0, h[0], h[1], h[2], h[3]);
            sts_v4(nbase + 16384 + st_c1, h[4], h[5], h[6], h[7]);
            sts_v4(nbase + 24576 + st_c0, l[0], l[1], l[2], l[3]);
            sts_v4(nbase + 24576 + st_c1, l[4], l[5], l[6], l[7]);
        }
        __syncthreads();
    }

    // ---- epilogue ----
    const int qr = lane >> 2;            // row within 8
    const int qc = (lane & 3) * 2;       // col pair within 8
    if (MODE == 0) {
        float* hbase = g_h + ((size_t)(e * MAXPE + m0 + wm * 64)) * H_ + n0 + wn * 32;
#pragma unroll
        for (int am = 0; am < 4; am++)
#pragma unroll
            for (int hh = 0; hh < 2; hh++) {
                float* dst = hbase + (size_t)(am * 16 + qr + hh * 8) * H_;
#pragma unroll
                for (int an = 0; an < 4; an++) {
                    const float* c = &acc[(am * 4 + an) * 4 + hh * 2];
                    float t0 = fmaxf(c[0], 0.f), t1 = fmaxf(c[1], 0.f);
                    float2 o = make_float2(t0 * t0, t1 * t1);
                    *(float2*)(dst + an * 8 + qc) = o;
                }
            }
    } else {
#pragma unroll
        for (int am = 0; am < 4; am++)
#pragma unroll
            for (int hh = 0; hh < 2; hh++) {
                const int m = m0 + wm * 64 + am * 16 + qr + hh * 8;
                if (m >= cnt) continue;
                const int tok = g_tok[e * MAXPE + m];
                const float wt = g_wt[e * MAXPE + m];
                float* orow = out + (size_t)tok * D_ + n0 + wn * 32;
#pragma unroll
                for (int an = 0; an < 4; an++) {
                    const float* c = &acc[(am * 4 + an) * 4 + hh * 2];
                    atomicAdd(orow + an * 8 + qc, wt * c[0]);
                    atomicAdd(orow + an * 8 + qc + 1, wt * c[1]);
                }
            }
    }
}

// ---------------- loss ----------------
__global__ void loss_kernel(float* __restrict__ out, int N, int out_size) {
    if (out_size <= N * D_) return;
    float loss = 0.0f;
    for (int e = 0; e < E_; e++)
        loss += (g_sumprob[e] / (float)N) * ((float)g_cnt[e] / (float)N);
    out[(size_t)N * D_] = loss * (float)E_;
}

// ---------------- launch ----------------
extern "C" void kernel_launch(void* const* d_in, const int* in_sizes, int n_in,
                              void* d_out, int out_size) {
    const float* x     = (const float*)d_in[0];
    const float* gw    = (const float*)d_in[1];
    const float* wfc   = (const float*)d_in[2];
    const float* wproj = (const float*)d_in[3];
    float* out = (float*)d_out;
    int N = in_sizes[0] / D_;  // 4096

    cudaFuncSetAttribute(moe_gemm_mma<0>, cudaFuncAttributeMaxDynamicSharedMemorySize,
                         SMEM_TOTAL);
    cudaFuncSetAttribute(moe_gemm_mma<1>, cudaFuncAttributeMaxDynamicSharedMemorySize,
                         SMEM_TOTAL);

    zero_kernel<<<1024, 256>>>(out, out_size);
    gate_kernel<<<(N + 7) / 8, 256>>>(x, gw, N);
    reduce_probs_kernel<<<E_, 256>>>(N);

    // x = N-tiles (fast-varying -> A-tile L2 reuse), y = M-tiles, z = expert
    dim3 g1(H_ / BN, MAXPE / BM, E_);
    moe_gemm_mma<0><<<g1, 256, SMEM_TOTAL>>>(x, wfc, nullptr, D_);

    dim3 g2(D_ / BN, MAXPE / BM, E_);
    moe_gemm_mma<1><<<g2, 256, SMEM_TOTAL>>>(nullptr, wproj, out, H_);

    loss_kernel<<<1, 1>>>(out, N, out_size);
}